// round 6
// baseline (speedup 1.0000x reference)
#include <cuda_runtime.h>

// ---------------------------------------------------------------------------
// MWDLSTMGCT: only the low-pass wavelet chain + LSTM-3 affect the output.
//   xl1 = avgpool2(sigmoid(x @ W1L^T + b1L))        (256 x 512)
//   xl2 = avgpool2(sigmoid(xl1 @ W2L^T + b2L))      (256 x 256)
//   h   = LSTM(xl2 as scalar sequence; Wih3,Whh3,b3), final hidden (256 x 100)
//   out = h @ Wout^T + bout                          (256 x 1)
// ---------------------------------------------------------------------------

#define NBATCH 256
#define HID    100
#define GATES  400   // 4*HID
#define TSTEPS 256

typedef unsigned long long ull;

__device__ __align__(16) float g_xl1[256 * 512];
__device__ __align__(16) float g_xl2[256 * 256];

// ----- f32x2 helpers (sm_103a packed fp32) ---------------------------------
__device__ __forceinline__ ull pack2(float a, float b) {
    ull r;
    asm("mov.b64 %0, {%1, %2};" : "=l"(r)
        : "r"(__float_as_uint(a)), "r"(__float_as_uint(b)));
    return r;
}
__device__ __forceinline__ ull dup2(float v) {
    ull r;
    asm("mov.b64 %0, {%1, %1};" : "=l"(r) : "r"(__float_as_uint(v)));
    return r;
}
__device__ __forceinline__ void fma2(ull& acc, ull a, ull b) {
    asm("fma.rn.f32x2 %0, %1, %2, %0;" : "+l"(acc) : "l"(a), "l"(b));
}
__device__ __forceinline__ float2 unpack2(ull v) {
    unsigned lo, hi;
    asm("mov.b64 {%0, %1}, %2;" : "=r"(lo), "=r"(hi) : "l"(v));
    return make_float2(__uint_as_float(lo), __uint_as_float(hi));
}
__device__ __forceinline__ float hsum2(ull v) {
    float2 p = unpack2(v);
    return p.x + p.y;
}

__device__ __forceinline__ float sigf(float x) { return 1.f / (1.f + __expf(-x)); }
__device__ __forceinline__ float tanh_fast(float x) {
    return 2.f / (1.f + __expf(-2.f * x)) - 1.f;
}

// ---------------------------------------------------------------------------
// Fused GEMM (C = A @ W^T), bias, sigmoid, avgpool2 along N.
// Tile 32(M) x 64(N), K-slices of 16, double-buffered smem, 2x4 microtile
// via packed f32x2 FMA. 256 threads, grid (N/64, M/32).
// A: [256][K], W: [N][K], out: [256][N/2]
// ---------------------------------------------------------------------------
template <int K>
__device__ __forceinline__ void gemm_sig_pool_body(
    const float* __restrict__ A, const float* __restrict__ W,
    const float* __restrict__ bias, float* __restrict__ out, int halfN)
{
    __shared__ __align__(16) float As[2][16][32];
    __shared__ __align__(16) float Bs[2][16][64];

    const int m0 = blockIdx.y * 32;
    const int n0 = blockIdx.x * 64;
    const int tid = threadIdx.x;
    const bool loadA = tid < 128;
    const int lm = tid >> 2;            // 0..63 (B rows); 0..31 for A when loadA
    const int lk = (tid & 3) * 4;       // 0,4,8,12 (k within slice)
    const int tx = tid & 15;            // 0..15 -> 4 N-cols
    const int ty = tid >> 4;            // 0..15 -> 2 M-rows

    const float* Aptr = A + (m0 + (lm & 31)) * K + lk;
    const float* Wptr = W + (n0 + lm) * K + lk;

    float4 a4 = loadA ? *(const float4*)(Aptr) : make_float4(0.f, 0.f, 0.f, 0.f);
    float4 b4 = *(const float4*)(Wptr);
    if (loadA) {
        As[0][lk + 0][lm] = a4.x; As[0][lk + 1][lm] = a4.y;
        As[0][lk + 2][lm] = a4.z; As[0][lk + 3][lm] = a4.w;
    }
    Bs[0][lk + 0][lm] = b4.x; Bs[0][lk + 1][lm] = b4.y;
    Bs[0][lk + 2][lm] = b4.z; Bs[0][lk + 3][lm] = b4.w;
    __syncthreads();

    ull acc[2][2];   // 2 rows x (2 packed col-pairs)
    acc[0][0] = 0ULL; acc[0][1] = 0ULL; acc[1][0] = 0ULL; acc[1][1] = 0ULL;
    const int NT = K / 16;

    for (int tI = 0; tI < NT; tI++) {
        const int cur = tI & 1;
        if (tI + 1 < NT) {
            if (loadA) a4 = *(const float4*)(Aptr + (tI + 1) * 16);
            b4 = *(const float4*)(Wptr + (tI + 1) * 16);
        }
        #pragma unroll
        for (int kk = 0; kk < 16; kk++) {
            float2 a2 = *(const float2*)&As[cur][kk][ty * 2];
            float4 bv = *(const float4*)&Bs[cur][kk][tx * 4];
            ull b01 = pack2(bv.x, bv.y);
            ull b23 = pack2(bv.z, bv.w);
            ull ad0 = dup2(a2.x);
            ull ad1 = dup2(a2.y);
            fma2(acc[0][0], ad0, b01);
            fma2(acc[0][1], ad0, b23);
            fma2(acc[1][0], ad1, b01);
            fma2(acc[1][1], ad1, b23);
        }
        if (tI + 1 < NT) {
            const int nb = cur ^ 1;
            if (loadA) {
                As[nb][lk + 0][lm] = a4.x; As[nb][lk + 1][lm] = a4.y;
                As[nb][lk + 2][lm] = a4.z; As[nb][lk + 3][lm] = a4.w;
            }
            Bs[nb][lk + 0][lm] = b4.x; Bs[nb][lk + 1][lm] = b4.y;
            Bs[nb][lk + 2][lm] = b4.z; Bs[nb][lk + 3][lm] = b4.w;
        }
        __syncthreads();
    }

    const float bn0 = bias[n0 + tx * 4 + 0];
    const float bn1 = bias[n0 + tx * 4 + 1];
    const float bn2 = bias[n0 + tx * 4 + 2];
    const float bn3 = bias[n0 + tx * 4 + 3];
    const int ocol = (n0 + tx * 4) >> 1;
    #pragma unroll
    for (int i = 0; i < 2; i++) {
        const int m = m0 + ty * 2 + i;
        float2 p01 = unpack2(acc[i][0]);
        float2 p23 = unpack2(acc[i][1]);
        float s0 = sigf(p01.x + bn0);
        float s1 = sigf(p01.y + bn1);
        float s2 = sigf(p23.x + bn2);
        float s3 = sigf(p23.y + bn3);
        out[m * halfN + ocol + 0] = 0.5f * (s0 + s1);
        out[m * halfN + ocol + 1] = 0.5f * (s2 + s3);
    }
}

__global__ void __launch_bounds__(256) gemm1_kernel(
    const float* __restrict__ A, const float* __restrict__ W,
    const float* __restrict__ bias)
{
    gemm_sig_pool_body<1024>(A, W, bias, g_xl1, 512);
}

__global__ void __launch_bounds__(256) gemm2_kernel(
    const float* __restrict__ W, const float* __restrict__ bias)
{
    gemm_sig_pool_body<512>(g_xl1, W, bias, g_xl2, 256);
}

// ---------------------------------------------------------------------------
// LSTM-3, persistent per-CTA, 2 batch rows per CTA.
// 416 threads; threads 0..399 each own one gate g with 50 pre-packed
// (w[2j],w[2j+1]) f32x2 weight pairs in registers. h kept per-row in shared
// (h0_s/h1_s) so 4 consecutive h values load as one LDS.128 = two ready
// f32x2 operands -> inner loop is 50 LDS.128 + 100 FFMA2 per step, no MOVs.
// Threads 0..199 run the gate nonlinearity epilogue (1 hidden unit x 1 row).
// ---------------------------------------------------------------------------
__global__ void __launch_bounds__(416, 1) lstm_kernel(
    const float* __restrict__ Wih, const float* __restrict__ Whh,
    const float* __restrict__ b3,  const float* __restrict__ Wout,
    const float* __restrict__ bout, float* __restrict__ out)
{
    const int r0 = blockIdx.x * 2;
    const int t = threadIdx.x;

    __shared__ __align__(16) float h0_s[HID];
    __shared__ __align__(16) float h1_s[HID];
    __shared__ float z_s[2][GATES];
    __shared__ float x_s[2][TSTEPS];
    __shared__ float red0[HID], red1[HID];

    ull wp[HID / 2];
    float wih_g = 0.f, bg = 0.f;
    if (t < GATES) {
        const float* wrow = Whh + t * HID;
        #pragma unroll
        for (int j = 0; j < HID / 2; j++)
            wp[j] = *(const ull*)(wrow + 2 * j);   // (w[2j], w[2j+1]) packed
        wih_g = Wih[t];
        bg = b3[t];
    }
    if (t < TSTEPS) {
        x_s[0][t] = g_xl2[r0 * TSTEPS + t];
        x_s[1][t] = g_xl2[(r0 + 1) * TSTEPS + t];
    }
    if (t < HID) { h0_s[t] = 0.f; h1_s[t] = 0.f; }
    float c_st = 0.f;   // cell state: thread t<100 -> row0 unit t; 100..199 -> row1 unit t-100
    __syncthreads();

    for (int step = 0; step < TSTEPS; step++) {
        if (t < GATES) {
            ull a0A = 0ULL, a0B = 0ULL, a1A = 0ULL, a1B = 0ULL;
            const ulonglong2* h0q = (const ulonglong2*)h0_s;
            const ulonglong2* h1q = (const ulonglong2*)h1_s;
            #pragma unroll
            for (int j = 0; j < HID / 4; j++) {       // 4 k per iter
                ulonglong2 hq0 = h0q[j];              // (h0[4j],h0[4j+1]) , (h0[4j+2],h0[4j+3])
                ulonglong2 hq1 = h1q[j];
                fma2(a0A, wp[2 * j],     hq0.x);
                fma2(a0B, wp[2 * j + 1], hq0.y);
                fma2(a1A, wp[2 * j],     hq1.x);
                fma2(a1B, wp[2 * j + 1], hq1.y);
            }
            z_s[0][t] = hsum2(a0A) + hsum2(a0B) + fmaf(wih_g, x_s[0][step], bg);
            z_s[1][t] = hsum2(a1A) + hsum2(a1B) + fmaf(wih_g, x_s[1][step], bg);
        }
        __syncthreads();
        if (t < 2 * HID) {
            const int row = (t >= HID) ? 1 : 0;
            const int j = t - row * HID;
            float iz = z_s[row][j];
            float fz = z_s[row][HID + j];
            float gz = z_s[row][2 * HID + j];
            float oz = z_s[row][3 * HID + j];
            c_st = sigf(fz) * c_st + sigf(iz) * tanh_fast(gz);
            float h = sigf(oz) * tanh_fast(c_st);
            if (row) h1_s[j] = h; else h0_s[j] = h;
        }
        __syncthreads();
    }

    // Final projection: out[r] = h_final . Wout + bout
    if (t < HID) {
        float w = Wout[t];
        red0[t] = h0_s[t] * w;
        red1[t] = h1_s[t] * w;
    }
    __syncthreads();
    if (t == 0) {
        float s = bout[0];
        for (int k = 0; k < HID; k++) s += red0[k];
        out[r0] = s;
    }
    if (t == 1) {
        float s = bout[0];
        for (int k = 0; k < HID; k++) s += red1[k];
        out[r0 + 1] = s;
    }
}

// ---------------------------------------------------------------------------
// Launch. Input order (metadata.txt): x, W1H, b1H, W1L, b1L, W2H, b2H, W2L,
// b2L, Wih1, Whh1, b1, Wih2, Whh2, b2, Wih3, Whh3, b3, Wout, bout.
// Only the low-pass + LSTM-3 inputs are used.
// ---------------------------------------------------------------------------
extern "C" void kernel_launch(void* const* d_in, const int* in_sizes, int n_in,
                              void* d_out, int out_size)
{
    const float* x    = (const float*)d_in[0];
    const float* W1L  = (const float*)d_in[3];
    const float* b1L  = (const float*)d_in[4];
    const float* W2L  = (const float*)d_in[7];
    const float* b2L  = (const float*)d_in[8];
    const float* Wih3 = (const float*)d_in[15];
    const float* Whh3 = (const float*)d_in[16];
    const float* b3   = (const float*)d_in[17];
    const float* Wout = (const float*)d_in[18];
    const float* bout = (const float*)d_in[19];
    float* out = (float*)d_out;

    dim3 grid1(16, 8);   // N=1024 -> 16 tiles, M=256/32 -> 8 tiles (128 CTAs)
    dim3 grid2(8, 8);    // N=512  -> 8 tiles
    gemm1_kernel<<<grid1, 256>>>(x, W1L, b1L);
    gemm2_kernel<<<grid2, 256>>>(W2L, b2L);
    lstm_kernel<<<128, 416>>>(Wih3, Whh3, b3, Wout, bout, out);
}

// round 8
// speedup vs baseline: 1.7890x; 1.7890x over previous
#include <cuda_runtime.h>

// ---------------------------------------------------------------------------
// MWDLSTMGCT: only the low-pass wavelet chain + LSTM-3 affect the output.
//   xl1 = avgpool2(sigmoid(x @ W1L^T + b1L))        (256 x 512)
//   xl2 = avgpool2(sigmoid(xl1 @ W2L^T + b2L))      (256 x 256)
//   h   = LSTM(xl2 as scalar sequence; Wih3,Whh3,b3), final hidden (256 x 100)
//   out = h @ Wout^T + bout                          (256 x 1)
// ---------------------------------------------------------------------------

#define NBATCH 256
#define HID    100
#define GATES  400   // 4*HID
#define TSTEPS 256

__device__ __align__(16) float g_xl1[256 * 512];
__device__ __align__(16) float g_xl2[256 * 256];

__device__ __forceinline__ float sigf(float x) { return 1.f / (1.f + __expf(-x)); }
// tanh(x) = 1 - 2/(exp(2x)+1); exact saturation at +/-inf, 2 MUFU + few ALU.
__device__ __forceinline__ float tanh_fast(float x) {
    return 1.f - 2.f / (__expf(2.f * x) + 1.f);
}

// ---------------------------------------------------------------------------
// Fused GEMM (C = A @ W^T), bias, sigmoid, avgpool2 along N.
// Tile 64(M) x 64(N), K-slices of 16, double-buffered smem.
// 512 threads, 4x2 microtile: tx=tid&31 -> cols 2tx..2tx+1, ty=tid>>5 ->
// rows 4ty..4ty+3. A-read is a float4 broadcast, B-read conflict-free LDS.64.
// A: [256][K], W: [N][K], out: [256][N/2]
// ---------------------------------------------------------------------------
template <int K>
__device__ __forceinline__ void gemm_sig_pool_body(
    const float* __restrict__ A, const float* __restrict__ W,
    const float* __restrict__ bias, float* __restrict__ out, int halfN)
{
    __shared__ __align__(16) float As[2][16][64];
    __shared__ __align__(16) float Bs[2][16][64];

    const int m0 = blockIdx.y * 64;
    const int n0 = blockIdx.x * 64;
    const int tid = threadIdx.x;

    // Loaders: threads 0..255 fill As, 256..511 fill Bs. Each loads one float4
    // per K-slice: lm = row in tile (0..63), lk = k offset (0,4,8,12).
    const bool isA = tid < 256;
    const int lt = isA ? tid : tid - 256;
    const int lm = lt >> 2;
    const int lk = (lt & 3) * 4;
    const float* Gptr = (isA ? A + (m0 + lm) * K : W + (n0 + lm) * K) + lk;
    float* Sbase = isA ? &As[0][0][0] : &Bs[0][0][0];

    float4 v4 = *(const float4*)(Gptr);
    Sbase[(lk + 0) * 64 + lm] = v4.x;
    Sbase[(lk + 1) * 64 + lm] = v4.y;
    Sbase[(lk + 2) * 64 + lm] = v4.z;
    Sbase[(lk + 3) * 64 + lm] = v4.w;
    __syncthreads();

    const int tx = tid & 31;   // 0..31 -> 2 N-cols
    const int ty = tid >> 5;   // 0..15 -> 4 M-rows

    float acc[4][2] = {};
    const int NT = K / 16;

    for (int tI = 0; tI < NT; tI++) {
        const int cur = tI & 1;
        if (tI + 1 < NT) v4 = *(const float4*)(Gptr + (tI + 1) * 16);
        #pragma unroll
        for (int kk = 0; kk < 16; kk++) {
            float4 av = *(const float4*)&As[cur][kk][ty * 4];
            float2 bv = *(const float2*)&Bs[cur][kk][tx * 2];
            acc[0][0] = fmaf(av.x, bv.x, acc[0][0]);
            acc[0][1] = fmaf(av.x, bv.y, acc[0][1]);
            acc[1][0] = fmaf(av.y, bv.x, acc[1][0]);
            acc[1][1] = fmaf(av.y, bv.y, acc[1][1]);
            acc[2][0] = fmaf(av.z, bv.x, acc[2][0]);
            acc[2][1] = fmaf(av.z, bv.y, acc[2][1]);
            acc[3][0] = fmaf(av.w, bv.x, acc[3][0]);
            acc[3][1] = fmaf(av.w, bv.y, acc[3][1]);
        }
        if (tI + 1 < NT) {
            const int nb = cur ^ 1;
            float* Sd = Sbase + nb * (16 * 64);
            Sd[(lk + 0) * 64 + lm] = v4.x;
            Sd[(lk + 1) * 64 + lm] = v4.y;
            Sd[(lk + 2) * 64 + lm] = v4.z;
            Sd[(lk + 3) * 64 + lm] = v4.w;
        }
        __syncthreads();
    }

    // bias + sigmoid + avgpool2 over the (2tx, 2tx+1) column pair.
    const float bn0 = bias[n0 + tx * 2 + 0];
    const float bn1 = bias[n0 + tx * 2 + 1];
    const int ocol = (n0 >> 1) + tx;
    #pragma unroll
    for (int i = 0; i < 4; i++) {
        const int m = m0 + ty * 4 + i;
        float s0 = sigf(acc[i][0] + bn0);
        float s1 = sigf(acc[i][1] + bn1);
        out[m * halfN + ocol] = 0.5f * (s0 + s1);
    }
}

__global__ void __launch_bounds__(512) gemm1_kernel(
    const float* __restrict__ A, const float* __restrict__ W,
    const float* __restrict__ bias)
{
    gemm_sig_pool_body<1024>(A, W, bias, g_xl1, 512);
}

__global__ void __launch_bounds__(512) gemm2_kernel(
    const float* __restrict__ W, const float* __restrict__ bias)
{
    gemm_sig_pool_body<512>(g_xl1, W, bias, g_xl2, 256);
}

// ---------------------------------------------------------------------------
// LSTM-3, persistent per-CTA, 2 batch rows per CTA, weights in registers.
// 416 threads; threads 0..399 each own gate g (Whh[g][0..99] in regs) and
// compute z for both rows (broadcast LDS.64 of packed (h0,h1)).
// Threads 0..199 run the gate nonlinearity (one (row, hidden-unit) each)
// with 2-MUFU sigmoid/tanh.
// ---------------------------------------------------------------------------
__global__ void __launch_bounds__(416, 1) lstm_kernel(
    const float* __restrict__ Wih, const float* __restrict__ Whh,
    const float* __restrict__ b3,  const float* __restrict__ Wout,
    const float* __restrict__ bout, float* __restrict__ out)
{
    const int r0 = blockIdx.x * 2;
    const int t = threadIdx.x;

    __shared__ __align__(8) float2 h_s[HID];
    __shared__ float z_s[2][GATES];
    __shared__ float x_s[2][TSTEPS];
    __shared__ float red0[HID], red1[HID];

    float wreg[HID];
    float wih_g = 0.f, bg = 0.f;
    if (t < GATES) {
        #pragma unroll
        for (int k = 0; k < HID; k++) wreg[k] = Whh[t * HID + k];
        wih_g = Wih[t];
        bg = b3[t];
    }
    if (t < TSTEPS) {
        x_s[0][t] = g_xl2[r0 * TSTEPS + t];
        x_s[1][t] = g_xl2[(r0 + 1) * TSTEPS + t];
    }
    if (t < HID) h_s[t] = make_float2(0.f, 0.f);
    float c_st = 0.f;   // t<100: row0 unit t; 100..199: row1 unit t-100
    __syncthreads();

    for (int step = 0; step < TSTEPS; step++) {
        if (t < GATES) {
            // two accumulators per row -> shorter serial FFMA chains
            float z0a = fmaf(wih_g, x_s[0][step], bg), z0b = 0.f;
            float z1a = fmaf(wih_g, x_s[1][step], bg), z1b = 0.f;
            #pragma unroll
            for (int k = 0; k < HID; k += 2) {
                float2 ha = h_s[k];
                float2 hb = h_s[k + 1];
                z0a = fmaf(wreg[k],     ha.x, z0a);
                z1a = fmaf(wreg[k],     ha.y, z1a);
                z0b = fmaf(wreg[k + 1], hb.x, z0b);
                z1b = fmaf(wreg[k + 1], hb.y, z1b);
            }
            z_s[0][t] = z0a + z0b;
            z_s[1][t] = z1a + z1b;
        }
        __syncthreads();
        if (t < 2 * HID) {
            const int row = (t >= HID) ? 1 : 0;
            const int j = t - row * HID;
            float iz = z_s[row][j];
            float fz = z_s[row][HID + j];
            float gz = z_s[row][2 * HID + j];
            float oz = z_s[row][3 * HID + j];
            c_st = sigf(fz) * c_st + sigf(iz) * tanh_fast(gz);
            float h = sigf(oz) * tanh_fast(c_st);
            ((float*)&h_s[j])[row] = h;
        }
        __syncthreads();
    }

    // Final projection: out[r] = h_final . Wout + bout
    if (t < HID) {
        float w = Wout[t];
        red0[t] = h_s[t].x * w;
        red1[t] = h_s[t].y * w;
    }
    __syncthreads();
    if (t == 0) {
        float s = bout[0];
        for (int k = 0; k < HID; k++) s += red0[k];
        out[r0] = s;
    }
    if (t == 1) {
        float s = bout[0];
        for (int k = 0; k < HID; k++) s += red1[k];
        out[r0 + 1] = s;
    }
}

// ---------------------------------------------------------------------------
// Launch. Input order (metadata.txt): x, W1H, b1H, W1L, b1L, W2H, b2H, W2L,
// b2L, Wih1, Whh1, b1, Wih2, Whh2, b2, Wih3, Whh3, b3, Wout, bout.
// Only the low-pass + LSTM-3 inputs are used.
// ---------------------------------------------------------------------------
extern "C" void kernel_launch(void* const* d_in, const int* in_sizes, int n_in,
                              void* d_out, int out_size)
{
    const float* x    = (const float*)d_in[0];
    const float* W1L  = (const float*)d_in[3];
    const float* b1L  = (const float*)d_in[4];
    const float* W2L  = (const float*)d_in[7];
    const float* b2L  = (const float*)d_in[8];
    const float* Wih3 = (const float*)d_in[15];
    const float* Whh3 = (const float*)d_in[16];
    const float* b3   = (const float*)d_in[17];
    const float* Wout = (const float*)d_in[18];
    const float* bout = (const float*)d_in[19];
    float* out = (float*)d_out;

    dim3 grid1(16, 4);   // N=1024/64, M=256/64
    dim3 grid2(8, 4);    // N=512/64
    gemm1_kernel<<<grid1, 512>>>(x, W1L, b1L);
    gemm2_kernel<<<grid2, 512>>>(W2L, b2L);
    lstm_kernel<<<128, 416>>>(Wih3, Whh3, b3, Wout, bout, out);
}